// round 2
// baseline (speedup 1.0000x reference)
#include <cuda_runtime.h>

// Problem constants
#define BSZ 8
#define CCH 128
#define NV  5
#define NH  224
#define NW  224
#define NK  2048
#define ND  64
#define HWSZ (NH*NW)          // 50176
#define VHW (NV*NH*NW)        // 250880

#define TILE 8                // points per tile (1 warp per point in MLP)
#define THREADS 256
#define NPTS (BSZ*NK)         // 16384
#define NTILES (NPTS/TILE)    // 2048
#define GRID (148*3)          // persistent: 3 blocks per SM
#define ITEMS ((TILE*CCH)/THREADS)   // 4 gather items per thread

struct GatherRegs {
    float f00[ITEMS], f01[ITEMS], f10[ITEMS], f11[ITEMS];
    float wx[ITEMS], wy[ITEMS];
};

__device__ __forceinline__ void issue_gather(int tile, int t,
                                             const float* __restrict__ fm,
                                             const float* __restrict__ pos,
                                             GatherRegs& g)
{
    #pragma unroll
    for (int it = 0; it < ITEMS; ++it) {
        int i = it * THREADS + t;
        int c = i & (CCH - 1);
        int p = i >> 7;
        int gp = tile * TILE + p;
        float p0 = __ldg(pos + gp * 3 + 0);
        float ry = __ldg(pos + gp * 3 + 1);
        float cx = __ldg(pos + gp * 3 + 2);
        int v = min(max((int)p0, 0), NV - 1);
        float y0f = floorf(ry);
        float x0f = floorf(cx);
        g.wy[it] = ry - y0f;
        g.wx[it] = cx - x0f;
        int y0 = min(max((int)y0f, 0), NH - 1);
        int dy = (min(y0 + 1, NH - 1) - y0) * NW;
        int x0 = min(max((int)x0f, 0), NW - 1);
        int dx = min(x0 + 1, NW - 1) - x0;
        int b = gp >> 11;  // gp / NK
        int base = b * (CCH * VHW) + v * HWSZ + y0 * NW + x0 + c * VHW;
        // streaming loads: zero reuse, don't pollute L2
        g.f00[it] = __ldcs(fm + base);
        g.f01[it] = __ldcs(fm + base + dx);
        g.f10[it] = __ldcs(fm + base + dy);
        g.f11[it] = __ldcs(fm + base + dy + dx);
    }
}

__global__ __launch_bounds__(THREADS, 3)
void peak_node_kernel(const float* __restrict__ fm,
                      const float* __restrict__ pos,
                      const float* __restrict__ W1,
                      const float* __restrict__ b1,
                      const float* __restrict__ W2,
                      const float* __restrict__ b2,
                      float* __restrict__ out)
{
    __shared__ float W1sh[CCH * ND];       // 32 KB, loaded once per persistent block
    __shared__ float samp[TILE][CCH];      // 4 KB
    __shared__ float hsh[TILE][ND + 2];    // ~2 KB, padded (float2-aligned rows)

    const int t = threadIdx.x;

    // stage W1 (published by the pipeline's syncthreads before first use)
    {
        const float4* W1v = reinterpret_cast<const float4*>(W1);
        float4* W1sv = reinterpret_cast<float4*>(W1sh);
        for (int i = t; i < (CCH * ND) / 4; i += THREADS)
            W1sv[i] = W1v[i];
    }

    int tile = blockIdx.x;
    GatherRegs g;
    issue_gather(tile, t, fm, pos, g);     // prologue loads in flight

    while (true) {
        __syncthreads();                   // prev MLP done reading samp
        // ---- combine in-flight loads -> samp ----
        #pragma unroll
        for (int it = 0; it < ITEMS; ++it) {
            int i = it * THREADS + t;
            int c = i & (CCH - 1);
            int p = i >> 7;
            float top = g.f00[it] + g.wx[it] * (g.f01[it] - g.f00[it]);
            float bot = g.f10[it] + g.wx[it] * (g.f11[it] - g.f10[it]);
            samp[p][c] = top + g.wy[it] * (bot - top);
        }
        __syncthreads();                   // samp (and W1sh) published

        // ---- issue next tile's gathers; they overlap the MLP below ----
        int next = tile + GRID;
        if (next < NTILES) issue_gather(next, t, fm, pos, g);

        // ---- MLP: warp p handles point p, 2 output dims per lane ----
        const int p  = t >> 5;
        const int d0 = (t & 31) * 2;

        float a0 = __ldg(b1 + d0);
        float a1 = __ldg(b1 + d0 + 1);
        #pragma unroll 8
        for (int c = 0; c < CCH; ++c) {
            float s = samp[p][c];          // warp-broadcast
            float2 w = *reinterpret_cast<const float2*>(&W1sh[c * ND + d0]);
            a0 = fmaf(s, w.x, a0);
            a1 = fmaf(s, w.y, a1);
        }
        a0 = fmaxf(a0, 0.f);
        a1 = fmaxf(a1, 0.f);
        *reinterpret_cast<float2*>(&hsh[p][d0]) = make_float2(a0, a1);
        __syncwarp();                      // hsh row is warp-private

        float o0 = __ldg(b2 + d0);
        float o1 = __ldg(b2 + d0 + 1);
        #pragma unroll 8
        for (int e = 0; e < ND; ++e) {
            float hv = hsh[p][e];          // warp-broadcast
            float2 w = __ldg(reinterpret_cast<const float2*>(&W2[e * ND + d0]));
            o0 = fmaf(hv, w.x, o0);
            o1 = fmaf(hv, w.y, o1);
        }

        // L2 norm over the warp's 64 dims
        float ss = o0 * o0 + o1 * o1;
        #pragma unroll
        for (int m = 16; m >= 1; m >>= 1)
            ss += __shfl_xor_sync(0xffffffffu, ss, m);
        float inv = 1.0f / fmaxf(sqrtf(ss), 1e-12f);

        int gp = tile * TILE + p;
        *reinterpret_cast<float2*>(&out[gp * ND + d0]) = make_float2(o0 * inv, o1 * inv);

        if (next >= NTILES) break;
        tile = next;
    }
}

extern "C" void kernel_launch(void* const* d_in, const int* in_sizes, int n_in,
                              void* d_out, int out_size)
{
    const float* fm  = (const float*)d_in[0];
    const float* pos = (const float*)d_in[1];
    const float* W1  = (const float*)d_in[2];
    const float* b1  = (const float*)d_in[3];
    const float* W2  = (const float*)d_in[4];
    const float* b2  = (const float*)d_in[5];
    float* out = (float*)d_out;

    peak_node_kernel<<<GRID, THREADS>>>(fm, pos, W1, b1, W2, b2, out);
}

// round 3
// speedup vs baseline: 1.0354x; 1.0354x over previous
#include <cuda_runtime.h>

// Problem constants
#define BSZ 8
#define CCH 128
#define NV  5
#define NH  224
#define NW  224
#define NK  2048
#define ND  64
#define HWSZ (NH*NW)          // 50176
#define VHW (NV*NH*NW)        // 250880

#define TILE 8                // points per block
#define THREADS 128
#define NPTS (BSZ*NK)         // 16384
#define GRID (NPTS/TILE)      // 2048 blocks

__global__ __launch_bounds__(THREADS, 10)
void peak_node_kernel(const float* __restrict__ fm,
                      const float* __restrict__ pos,
                      const float* __restrict__ W1,
                      const float* __restrict__ b1,
                      const float* __restrict__ W2,
                      const float* __restrict__ b2,
                      float* __restrict__ out)
{
    __shared__ float samp[TILE][CCH + 4];   // padded: MLP's 2-row broadcast hits distinct banks
    __shared__ float hsh[TILE][ND + 4];
    __shared__ int   pbase[TILE];
    __shared__ int   pdx[TILE];
    __shared__ int   pdyw[TILE];
    __shared__ float pwx[TILE];
    __shared__ float pwy[TILE];

    const int t = threadIdx.x;

    // ---- per-point setup (first TILE threads) ----
    if (t < TILE) {
        int gp = blockIdx.x * TILE + t;
        float p0 = pos[gp * 3 + 0];
        float ry = pos[gp * 3 + 1];
        float cx = pos[gp * 3 + 2];
        int v = min(max((int)p0, 0), NV - 1);
        float y0f = floorf(ry);
        float x0f = floorf(cx);
        pwy[t] = ry - y0f;
        pwx[t] = cx - x0f;
        int y0 = min(max((int)y0f, 0), NH - 1);
        int y1 = min(y0 + 1, NH - 1);
        int x0 = min(max((int)x0f, 0), NW - 1);
        int x1 = min(x0 + 1, NW - 1);
        int b = gp >> 11;                    // gp / NK
        pbase[t] = b * (CCH * VHW) + v * HWSZ + y0 * NW + x0;
        pdx[t]   = x1 - x0;
        pdyw[t]  = (y1 - y0) * NW;
    }
    __syncthreads();

    // ---- phase 1: bilinear gather. Iteration p: 128 threads cover point p's channels ----
    #pragma unroll
    for (int p = 0; p < TILE; ++p) {
        int c = t;                           // channel = lane-linear thread id
        int base = pbase[p] + c * VHW;       // pbase/dx/dy/wx/wy are uniform per iteration
        int dx = pdx[p];
        int dy = pdyw[p];
        float f00 = __ldg(fm + base);
        float f01 = __ldg(fm + base + dx);
        float f10 = __ldg(fm + base + dy);
        float f11 = __ldg(fm + base + dy + dx);
        float wx = pwx[p];
        float wy = pwy[p];
        float top = f00 + wx * (f01 - f00);
        float bot = f10 + wx * (f11 - f10);
        samp[p][c] = top + wy * (bot - top);
    }
    __syncthreads();

    // ---- phase 2: MLP. 16 threads per point, 4 dims each; W1/W2 via L1-resident __ldg ----
    const int p  = t >> 4;                   // 0..7
    const int db = (t & 15) * 4;             // 0,4,...,60

    float a0 = __ldg(b1 + db + 0);
    float a1 = __ldg(b1 + db + 1);
    float a2 = __ldg(b1 + db + 2);
    float a3 = __ldg(b1 + db + 3);
    #pragma unroll 8
    for (int c = 0; c < CCH; ++c) {
        float s = samp[p][c];                // 2-address broadcast, distinct banks (padding)
        float4 w = __ldg(reinterpret_cast<const float4*>(&W1[c * ND + db]));
        a0 = fmaf(s, w.x, a0);
        a1 = fmaf(s, w.y, a1);
        a2 = fmaf(s, w.z, a2);
        a3 = fmaf(s, w.w, a3);
    }
    float4 hv;
    hv.x = fmaxf(a0, 0.f);
    hv.y = fmaxf(a1, 0.f);
    hv.z = fmaxf(a2, 0.f);
    hv.w = fmaxf(a3, 0.f);
    *reinterpret_cast<float4*>(&hsh[p][db]) = hv;
    __syncthreads();

    float o0 = __ldg(b2 + db + 0);
    float o1 = __ldg(b2 + db + 1);
    float o2 = __ldg(b2 + db + 2);
    float o3 = __ldg(b2 + db + 3);
    #pragma unroll 8
    for (int e = 0; e < ND; ++e) {
        float hval = hsh[p][e];
        float4 w = __ldg(reinterpret_cast<const float4*>(&W2[e * ND + db]));
        o0 = fmaf(hval, w.x, o0);
        o1 = fmaf(hval, w.y, o1);
        o2 = fmaf(hval, w.z, o2);
        o3 = fmaf(hval, w.w, o3);
    }

    // L2 norm across the point's 64 dims: reduce over the 16 lanes owning this point
    float ss = o0 * o0 + o1 * o1 + o2 * o2 + o3 * o3;
    #pragma unroll
    for (int m = 8; m >= 1; m >>= 1)
        ss += __shfl_xor_sync(0xffffffffu, ss, m);

    float inv = 1.0f / fmaxf(sqrtf(ss), 1e-12f);

    int gp = blockIdx.x * TILE + p;
    float4 ov;
    ov.x = o0 * inv;
    ov.y = o1 * inv;
    ov.z = o2 * inv;
    ov.w = o3 * inv;
    *reinterpret_cast<float4*>(&out[gp * ND + db]) = ov;
}

extern "C" void kernel_launch(void* const* d_in, const int* in_sizes, int n_in,
                              void* d_out, int out_size)
{
    const float* fm  = (const float*)d_in[0];
    const float* pos = (const float*)d_in[1];
    const float* W1  = (const float*)d_in[2];
    const float* b1  = (const float*)d_in[3];
    const float* W2  = (const float*)d_in[4];
    const float* b2  = (const float*)d_in[5];
    float* out = (float*)d_out;

    peak_node_kernel<<<GRID, THREADS>>>(fm, pos, W1, b1, W2, b2, out);
}

// round 6
// speedup vs baseline: 1.1135x; 1.0755x over previous
#include <cuda_runtime.h>

// Problem constants
#define BSZ 8
#define CCH 128
#define NV  5
#define NH  224
#define NW  224
#define NK  2048
#define ND  64
#define HWSZ (NH*NW)          // 50176
#define VHW (NV*NH*NW)        // 250880

#define TILE 8                // points per buffer (1 warp = 1 point in MLP)
#define NBUF 2
#define PTSBLK (TILE*NBUF)    // 16 points per block
#define THREADS 256
#define NPTS (BSZ*NK)         // 16384
#define GRID (NPTS/PTSBLK)    // 1024 blocks
#define ITEMS ((TILE*CCH)/THREADS)   // 4 (pt,ch) items per thread per buffer

__global__ __launch_bounds__(THREADS, 4)
void peak_node_kernel(const float* __restrict__ fm,
                      const float* __restrict__ pos,
                      const float* __restrict__ W1,
                      const float* __restrict__ b1,
                      const float* __restrict__ W2,
                      const float* __restrict__ b2,
                      float* __restrict__ out)
{
    __shared__ float W1sh[CCH * ND];          // 32 KB
    __shared__ float samp[NBUF][TILE][CCH];   // 8 KB
    __shared__ float hsh[TILE][ND + 2];       // reused across buffers
    __shared__ int   pbase[PTSBLK];
    __shared__ int   pdx[PTSBLK];
    __shared__ int   pdyw[PTSBLK];
    __shared__ float pwx[PTSBLK];
    __shared__ float pwy[PTSBLK];

    const int t = threadIdx.x;

    // ---- stage W1 into shared ----
    {
        const float4* W1v = reinterpret_cast<const float4*>(W1);
        float4* W1sv = reinterpret_cast<float4*>(W1sh);
        #pragma unroll
        for (int i = t; i < (CCH * ND) / 4; i += THREADS)
            W1sv[i] = W1v[i];
    }

    // ---- per-point setup for all 16 points ----
    if (t < PTSBLK) {
        int gp = blockIdx.x * PTSBLK + t;
        float p0 = pos[gp * 3 + 0];
        float ry = pos[gp * 3 + 1];
        float cx = pos[gp * 3 + 2];
        int v = min(max((int)p0, 0), NV - 1);
        float y0f = floorf(ry);
        float x0f = floorf(cx);
        pwy[t] = ry - y0f;
        pwx[t] = cx - x0f;
        int y0 = min(max((int)y0f, 0), NH - 1);
        int y1 = min(y0 + 1, NH - 1);
        int x0 = min(max((int)x0f, 0), NW - 1);
        int x1 = min(x0 + 1, NW - 1);
        int b = gp >> 11;                      // gp / NK
        pbase[t] = b * (CCH * VHW) + v * HWSZ + y0 * NW + x0;
        pdx[t]   = x1 - x0;
        pdyw[t]  = (y1 - y0) * NW;
    }
    __syncthreads();

    float f00[ITEMS], f01[ITEMS], f10[ITEMS], f11[ITEMS];

    // ---- issue buffer A loads (16 LDG/thread, batched) ----
    #pragma unroll
    for (int it = 0; it < ITEMS; ++it) {
        int i = it * THREADS + t;
        int c = i & (CCH - 1);
        int p = i >> 7;                        // 0..7 (buffer A points)
        int base = pbase[p] + c * VHW;
        int dx = pdx[p];
        int dy = pdyw[p];
        f00[it] = __ldg(fm + base);
        f01[it] = __ldg(fm + base + dx);
        f10[it] = __ldg(fm + base + dy);
        f11[it] = __ldg(fm + base + dy + dx);
    }
    // ---- combine A ----
    #pragma unroll
    for (int it = 0; it < ITEMS; ++it) {
        int i = it * THREADS + t;
        int c = i & (CCH - 1);
        int p = i >> 7;
        float wx = pwx[p], wy = pwy[p];
        float top = f00[it] + wx * (f01[it] - f00[it]);
        float bot = f10[it] + wx * (f11[it] - f10[it]);
        samp[0][p][c] = top + wy * (bot - top);
    }
    // ---- issue buffer B loads (in flight during MLP(A)) ----
    #pragma unroll
    for (int it = 0; it < ITEMS; ++it) {
        int i = it * THREADS + t;
        int c = i & (CCH - 1);
        int p = (i >> 7) + TILE;               // 8..15 (buffer B points)
        int base = pbase[p] + c * VHW;
        int dx = pdx[p];
        int dy = pdyw[p];
        f00[it] = __ldg(fm + base);
        f01[it] = __ldg(fm + base + dx);
        f10[it] = __ldg(fm + base + dy);
        f11[it] = __ldg(fm + base + dy + dx);
    }
    __syncthreads();                           // samp[0] + W1sh published

    // ---- MLP: warp p handles one point; 2 output dims per lane ----
    const int p  = t >> 5;                     // warp id 0..7
    const int d0 = (t & 31) * 2;               // 0,2,...,62

    #pragma unroll
    for (int buf = 0; buf < NBUF; ++buf) {
        // layer 1: h = relu(samp @ W1 + b1)
        float a0 = __ldg(b1 + d0);
        float a1 = __ldg(b1 + d0 + 1);
        #pragma unroll 8
        for (int c = 0; c < CCH; ++c) {
            float s = samp[buf][p][c];         // warp broadcast
            float2 w = *reinterpret_cast<const float2*>(&W1sh[c * ND + d0]);
            a0 = fmaf(s, w.x, a0);
            a1 = fmaf(s, w.y, a1);
        }
        a0 = fmaxf(a0, 0.f);
        a1 = fmaxf(a1, 0.f);
        *reinterpret_cast<float2*>(&hsh[p][d0]) = make_float2(a0, a1);
        __syncwarp();                          // hsh row is warp-private

        // layer 2: out = h @ W2 + b2 (W2 L1-resident)
        float o0 = __ldg(b2 + d0);
        float o1 = __ldg(b2 + d0 + 1);
        #pragma unroll 8
        for (int e = 0; e < ND; ++e) {
            float hv = hsh[p][e];              // warp broadcast
            float2 w = __ldg(reinterpret_cast<const float2*>(&W2[e * ND + d0]));
            o0 = fmaf(hv, w.x, o0);
            o1 = fmaf(hv, w.y, o1);
        }

        // L2 norm over this warp's 64 dims
        float ss = o0 * o0 + o1 * o1;
        #pragma unroll
        for (int m = 16; m >= 1; m >>= 1)
            ss += __shfl_xor_sync(0xffffffffu, ss, m);
        float inv = 1.0f / fmaxf(sqrtf(ss), 1e-12f);

        int gp = blockIdx.x * PTSBLK + buf * TILE + p;
        *reinterpret_cast<float2*>(&out[gp * ND + d0]) = make_float2(o0 * inv, o1 * inv);

        if (buf == 0) {
            // ---- combine B (loads completed under MLP(A)) ----
            #pragma unroll
            for (int it = 0; it < ITEMS; ++it) {
                int i = it * THREADS + t;
                int c = i & (CCH - 1);
                int pp = (i >> 7) + TILE;
                float wx = pwx[pp], wy = pwy[pp];
                float top = f00[it] + wx * (f01[it] - f00[it]);
                float bot = f10[it] + wx * (f11[it] - f10[it]);
                samp[1][(i >> 7)][c] = top + wy * (bot - top);
            }
            __syncthreads();                   // samp[1] published, hsh free for reuse
        }
    }
}

extern "C" void kernel_launch(void* const* d_in, const int* in_sizes, int n_in,
                              void* d_out, int out_size)
{
    const float* fm  = (const float*)d_in[0];
    const float* pos = (const float*)d_in[1];
    const float* W1  = (const float*)d_in[2];
    const float* b1  = (const float*)d_in[3];
    const float* W2  = (const float*)d_in[4];
    const float* b2  = (const float*)d_in[5];
    float* out = (float*)d_out;

    peak_node_kernel<<<GRID, THREADS>>>(fm, pos, W1, b1, W2, b2, out);
}

// round 9
// speedup vs baseline: 1.1534x; 1.0358x over previous
#include <cuda_runtime.h>

// Problem constants
#define BSZ 8
#define CCH 128
#define NV  5
#define NH  224
#define NW  224
#define NK  2048
#define ND  64
#define HWSZ (NH*NW)          // 50176
#define VHW (NV*NH*NW)        // 250880

#define TILE 16               // points per block
#define THREADS 256
#define NPTS (BSZ*NK)         // 16384
#define YB   28               // y-blocks of 8 rows
#define NBKT (BSZ*NV*YB)      // 1120 buckets
#define NBKT_PAD 1280         // 256 threads * 5 chunk

// sort scratch (device globals: no allocation)
__device__ int g_hist[NBKT_PAD];
__device__ int g_perm[NPTS];

__device__ __forceinline__ int point_bucket(const float* __restrict__ pos, int gp)
{
    float p0 = __ldg(pos + gp * 3 + 0);
    float ry = __ldg(pos + gp * 3 + 1);
    int v  = min(max((int)p0, 0), NV - 1);
    int y0 = min(max((int)floorf(ry), 0), NH - 1);
    int b  = gp >> 11;                 // gp / NK
    return b * (NV * YB) + v * YB + (y0 >> 3);
}

__global__ void zero_hist_kernel()
{
    int i = blockIdx.x * blockDim.x + threadIdx.x;
    if (i < NBKT_PAD) g_hist[i] = 0;
}

__global__ void hist_kernel(const float* __restrict__ pos)
{
    int gp = blockIdx.x * blockDim.x + threadIdx.x;
    if (gp < NPTS) atomicAdd(&g_hist[point_bucket(pos, gp)], 1);
}

// single block, 256 threads: exclusive scan of g_hist[0..NBKT_PAD) in place.
// Each thread serially scans a 5-entry chunk; chunk sums get a warp+block scan.
#define CHUNK 5
__global__ void scan_kernel()
{
    __shared__ int warpsum[8];
    int t = threadIdx.x;
    int w = t >> 5;
    int l = t & 31;

    int v[CHUNK];
    int sum = 0;
    #pragma unroll
    for (int i = 0; i < CHUNK; ++i) {
        v[i] = g_hist[t * CHUNK + i];
        sum += v[i];
    }

    // warp inclusive scan of per-thread sums
    int inc = sum;
    #pragma unroll
    for (int d = 1; d < 32; d <<= 1) {
        int n = __shfl_up_sync(0xffffffffu, inc, d);
        if (l >= d) inc += n;
    }
    if (l == 31) warpsum[w] = inc;
    __syncthreads();

    int woff = 0;
    if (w > 0) {
        #pragma unroll
        for (int i = 0; i < 7; ++i)
            if (i < w) woff += warpsum[i];
    }

    int excl = woff + inc - sum;       // exclusive prefix of this thread's chunk
    #pragma unroll
    for (int i = 0; i < CHUNK; ++i) {
        g_hist[t * CHUNK + i] = excl;
        excl += v[i];
    }
}

__global__ void scatter_kernel(const float* __restrict__ pos)
{
    int gp = blockIdx.x * blockDim.x + threadIdx.x;
    if (gp < NPTS) {
        int rank = atomicAdd(&g_hist[point_bucket(pos, gp)], 1);
        g_perm[rank] = gp;
    }
}

// ---- main kernel: identical to the 100.8us R1 kernel, plus perm indirection ----
__global__ __launch_bounds__(THREADS, 2)
void peak_node_kernel(const float* __restrict__ fm,
                      const float* __restrict__ pos,
                      const float* __restrict__ W1,
                      const float* __restrict__ b1,
                      const float* __restrict__ W2,
                      const float* __restrict__ b2,
                      float* __restrict__ out)
{
    __shared__ float W1sh[CCH * ND];          // 32 KB, row-major [c][d]
    __shared__ float samp[TILE][CCH + 4];
    __shared__ float hsh[TILE][ND + 4];
    __shared__ int   pgp[TILE];
    __shared__ int   pbase[TILE];
    __shared__ int   pdx[TILE];
    __shared__ int   pdyw[TILE];
    __shared__ float pwx[TILE];
    __shared__ float pwy[TILE];

    const int t = threadIdx.x;

    // ---- stage W1 into shared (float4) ----
    {
        const float4* W1v = reinterpret_cast<const float4*>(W1);
        float4* W1sv = reinterpret_cast<float4*>(W1sh);
        #pragma unroll
        for (int i = t; i < (CCH * ND) / 4; i += THREADS)
            W1sv[i] = W1v[i];
    }

    // ---- per-point setup (first TILE threads) ----
    if (t < TILE) {
        int gp = g_perm[blockIdx.x * TILE + t];    // spatially clustered point
        pgp[t] = gp;
        float p0 = pos[gp * 3 + 0];
        float ry = pos[gp * 3 + 1];
        float cx = pos[gp * 3 + 2];
        int v = min(max((int)p0, 0), NV - 1);
        float y0f = floorf(ry);
        float x0f = floorf(cx);
        pwy[t] = ry - y0f;
        pwx[t] = cx - x0f;
        int y0 = min(max((int)y0f, 0), NH - 1);
        int y1 = min(y0 + 1, NH - 1);
        int x0 = min(max((int)x0f, 0), NW - 1);
        int x1 = min(x0 + 1, NW - 1);
        int b = gp >> 11;
        pbase[t] = b * (CCH * VHW) + v * HWSZ + y0 * NW + x0;
        pdx[t]   = x1 - x0;
        pdyw[t]  = (y1 - y0) * NW;
    }
    __syncthreads();

    // ---- phase 1: bilinear gather ----
    #pragma unroll
    for (int it = 0; it < (TILE * CCH) / THREADS; ++it) {
        int i = it * THREADS + t;
        int c = i & (CCH - 1);
        int p = i >> 7;
        int base = pbase[p] + c * VHW;
        int dx = pdx[p];
        int dy = pdyw[p];
        float f00 = __ldg(fm + base);
        float f01 = __ldg(fm + base + dx);
        float f10 = __ldg(fm + base + dy);
        float f11 = __ldg(fm + base + dy + dx);
        float wx = pwx[p];
        float wy = pwy[p];
        float top = f00 + wx * (f01 - f00);
        float bot = f10 + wx * (f11 - f10);
        samp[p][c] = top + wy * (bot - top);
    }
    __syncthreads();

    // ---- phase 2: MLP. 16 threads per point, 4 dims each ----
    const int p  = t >> 4;            // 0..15
    const int db = (t & 15) * 4;      // 0,4,...,60

    float a0 = b1[db + 0];
    float a1 = b1[db + 1];
    float a2 = b1[db + 2];
    float a3 = b1[db + 3];
    #pragma unroll 8
    for (int c = 0; c < CCH; ++c) {
        float s = samp[p][c];
        float4 w = *reinterpret_cast<const float4*>(&W1sh[c * ND + db]);
        a0 = fmaf(s, w.x, a0);
        a1 = fmaf(s, w.y, a1);
        a2 = fmaf(s, w.z, a2);
        a3 = fmaf(s, w.w, a3);
    }
    float4 hv;
    hv.x = fmaxf(a0, 0.f);
    hv.y = fmaxf(a1, 0.f);
    hv.z = fmaxf(a2, 0.f);
    hv.w = fmaxf(a3, 0.f);
    *reinterpret_cast<float4*>(&hsh[p][db]) = hv;
    __syncthreads();

    float o0 = __ldg(b2 + db + 0);
    float o1 = __ldg(b2 + db + 1);
    float o2 = __ldg(b2 + db + 2);
    float o3 = __ldg(b2 + db + 3);
    #pragma unroll 8
    for (int e = 0; e < ND; ++e) {
        float hval = hsh[p][e];
        float4 w = __ldg(reinterpret_cast<const float4*>(&W2[e * ND + db]));
        o0 = fmaf(hval, w.x, o0);
        o1 = fmaf(hval, w.y, o1);
        o2 = fmaf(hval, w.z, o2);
        o3 = fmaf(hval, w.w, o3);
    }

    float ss = o0 * o0 + o1 * o1 + o2 * o2 + o3 * o3;
    #pragma unroll
    for (int m = 8; m >= 1; m >>= 1)
        ss += __shfl_xor_sync(0xffffffffu, ss, m);

    float inv = 1.0f / fmaxf(sqrtf(ss), 1e-12f);

    int gp = pgp[p];
    float4 ov;
    ov.x = o0 * inv;
    ov.y = o1 * inv;
    ov.z = o2 * inv;
    ov.w = o3 * inv;
    *reinterpret_cast<float4*>(&out[gp * ND + db]) = ov;
}

extern "C" void kernel_launch(void* const* d_in, const int* in_sizes, int n_in,
                              void* d_out, int out_size)
{
    const float* fm  = (const float*)d_in[0];
    const float* pos = (const float*)d_in[1];
    const float* W1  = (const float*)d_in[2];
    const float* b1  = (const float*)d_in[3];
    const float* W2  = (const float*)d_in[4];
    const float* b2  = (const float*)d_in[5];
    float* out = (float*)d_out;

    zero_hist_kernel<<<(NBKT_PAD + 255) / 256, 256>>>();
    hist_kernel<<<NPTS / 256, 256>>>(pos);
    scan_kernel<<<1, 256>>>();
    scatter_kernel<<<NPTS / 256, 256>>>(pos);
    peak_node_kernel<<<NPTS / TILE, THREADS>>>(fm, pos, W1, b1, W2, b2, out);
}